// round 2
// baseline (speedup 1.0000x reference)
#include <cuda_runtime.h>
#include <cstdint>

#define N_MAX   50000
#define OUT     128
#define EDIM    64

// ---------------- device scratch (no cudaMalloc allowed) ----------------
__device__ __align__(16) float g_W1[128 * 128];   // Wx @ Wm_top   [128,128]
__device__ __align__(16) float g_W2[64 * 128];    // We @ Wm_bot   [64,128]
__device__ __align__(16) float g_c[128];          // fused bias
__device__ __align__(16) float g_A[(size_t)N_MAX * OUT];    // x @ W1
__device__ __align__(16) float g_agg[(size_t)N_MAX * OUT];  // scatter target
__device__ int g_is64;

// ---------------- f32x2 helpers ----------------
__device__ __forceinline__ unsigned long long pk2(float x, float y) {
    unsigned long long r;
    asm("mov.b64 %0, {%1, %2};" : "=l"(r) : "f"(x), "f"(y));
    return r;
}
__device__ __forceinline__ void upk2(unsigned long long v, float& x, float& y) {
    asm("mov.b64 {%0, %1}, %2;" : "=f"(x), "=f"(y) : "l"(v));
}
__device__ __forceinline__ void ffma2(unsigned long long& acc, unsigned long long w,
                                      unsigned long long a) {
    asm("fma.rn.f32x2 %0, %1, %2, %0;" : "+l"(acc) : "l"(w), "l"(a));
}

// ---------------- detect int64 vs int32 edge_index ----------------
__global__ void detect_kernel(const int* __restrict__ idx) {
    if (blockIdx.x == 0 && threadIdx.x == 0) {
        int ok = 1;
        for (int i = 1; i < 64; i += 2)
            if (idx[i] != 0) ok = 0;
        g_is64 = ok;
    }
}

// ---------------- fold the three weight matrices ----------------
__global__ void prep_kernel(const float* __restrict__ Wx, const float* __restrict__ bx,
                            const float* __restrict__ We, const float* __restrict__ be,
                            const float* __restrict__ Wm, const float* __restrict__ bm) {
    __shared__ float row[128];
    __shared__ float row2[128];
    const int b = blockIdx.x;
    const int j = threadIdx.x;  // 128 threads
    if (b < 128) {
        row[j] = Wx[b * 128 + j];
        __syncthreads();
        float s = 0.f;
#pragma unroll 8
        for (int k = 0; k < 128; k++) s = fmaf(row[k], Wm[k * 128 + j], s);
        g_W1[b * 128 + j] = s;
    } else if (b < 192) {
        const int i = b - 128;
        row[j] = We[i * 128 + j];
        __syncthreads();
        float s = 0.f;
#pragma unroll 8
        for (int k = 0; k < 128; k++) s = fmaf(row[k], Wm[(128 + k) * 128 + j], s);
        g_W2[i * 128 + j] = s;
    } else {
        row[j] = bx[j];
        row2[j] = be[j];
        __syncthreads();
        float s = bm[j];
#pragma unroll 8
        for (int k = 0; k < 128; k++) {
            s = fmaf(row[k], Wm[k * 128 + j], s);
            s = fmaf(row2[k], Wm[(128 + k) * 128 + j], s);
        }
        g_c[j] = s;
    }
}

// ---------------- zero the aggregation buffer ----------------
__global__ void zero_kernel(int n4) {
    int i = blockIdx.x * blockDim.x + threadIdx.x;
    const int stride = gridDim.x * blockDim.x;
    float4 z = make_float4(0.f, 0.f, 0.f, 0.f);
    for (; i < n4; i += stride) reinterpret_cast<float4*>(g_agg)[i] = z;
}

// ---------------- node GEMM: A = x @ W1 (shfl version, T=8) ----------------
__global__ void __launch_bounds__(256) node_kernel(const float* __restrict__ x, int N) {
    extern __shared__ float w1s[];  // 128*128 floats
    const int tid = threadIdx.x;
    for (int i = tid; i < 128 * 128; i += blockDim.x) w1s[i] = g_W1[i];
    __syncthreads();

    const int lane = tid & 31;
    const int gw = (blockIdx.x * blockDim.x + tid) >> 5;
    const int nw = (gridDim.x * blockDim.x) >> 5;
    constexpr int T = 8;

    for (int base = gw * T; base < N; base += nw * T) {
        const int cnt = min(T, N - base);
        float a[T][4];
#pragma unroll
        for (int t = 0; t < T; t++) {
            const int r = base + (t < cnt ? t : 0);
#pragma unroll
            for (int q = 0; q < 4; q++) a[t][q] = x[(size_t)r * 128 + q * 32 + lane];
        }
        unsigned long long acc0[T], acc1[T];
#pragma unroll
        for (int t = 0; t < T; t++) { acc0[t] = 0ull; acc1[t] = 0ull; }

#pragma unroll
        for (int q = 0; q < 4; q++) {
#pragma unroll 8
            for (int kk = 0; kk < 32; kk++) {
                const int k = q * 32 + kk;
                const float4 w = *reinterpret_cast<const float4*>(&w1s[k * 128 + lane * 4]);
                const unsigned long long w01 = pk2(w.x, w.y);
                const unsigned long long w23 = pk2(w.z, w.w);
#pragma unroll
                for (int t = 0; t < T; t++) {
                    const float av = __shfl_sync(0xffffffffu, a[t][q], kk);
                    const unsigned long long aa = pk2(av, av);
                    ffma2(acc0[t], w01, aa);
                    ffma2(acc1[t], w23, aa);
                }
            }
        }
#pragma unroll
        for (int t = 0; t < T; t++) {
            if (t < cnt) {
                float o0, o1, o2, o3;
                upk2(acc0[t], o0, o1);
                upk2(acc1[t], o2, o3);
                *reinterpret_cast<float4*>(&g_A[(size_t)(base + t) * 128 + lane * 4]) =
                    make_float4(o0, o1, o2, o3);
            }
        }
    }
}

// ---------------- edge kernel: msg + scatter, SHFL-free ----------------
// Warp handles T=16 edges. Edge attrs staged TRANSPOSED + DUPLICATED in smem
// (row k holds float2(v,v) per edge), so the per-k broadcast is uniform LDS
// (1 crossbar cyc) delivering ready f32x2 multiplier pairs. No SHFL, no MOVs.
#define EAT_STRIDE 36   // floats per staged row: 32 (16 dup pairs) + 4 pad, 16B aligned
__global__ void __launch_bounds__(256) edge_kernel(const float* __restrict__ ea,
                                                   const int* __restrict__ idx, int E) {
    extern __shared__ float sm[];
    float* w2s = sm;                          // 64*128 = 8192 floats
    float* cs = sm + 64 * 128;                // 128 floats
    float* eas = sm + 64 * 128 + 128;         // 8 warps * 64 * EAT_STRIDE
    const int tid = threadIdx.x;
    for (int i = tid; i < EDIM * OUT; i += 256) w2s[i] = g_W2[i];
    if (tid < OUT) cs[tid] = g_c[tid];
    __syncthreads();

    const int lane = tid & 31;
    const int warp = tid >> 5;
    float* my = eas + warp * (64 * EAT_STRIDE);
    const float4 cv = *reinterpret_cast<const float4*>(&cs[lane * 4]);
    const int is64 = g_is64;
    const int gw = blockIdx.x * 8 + warp;
    const int nw = gridDim.x * 8;
    constexpr int T = 16;

    for (long long base = (long long)gw * T; base < E; base += (long long)nw * T) {
        const int cnt = (int)min((long long)T, (long long)E - base);

        // ---- stage edge attrs: transposed, duplicated ----
#pragma unroll
        for (int t = 0; t < T; t++) {
            const long long e = base + (t < cnt ? t : cnt - 1);
            const float v0 = ea[e * 64 + lane];
            const float v1 = ea[e * 64 + 32 + lane];
            *reinterpret_cast<float2*>(&my[lane * EAT_STRIDE + 2 * t]) =
                make_float2(v0, v0);
            *reinterpret_cast<float2*>(&my[(lane + 32) * EAT_STRIDE + 2 * t]) =
                make_float2(v1, v1);
        }
        __syncwarp();

        unsigned long long acc0[T], acc1[T];
#pragma unroll
        for (int t = 0; t < T; t++) { acc0[t] = 0ull; acc1[t] = 0ull; }

        // ---- main GEMM loop: per k, 1 LDS.128 (W2 row) + 4 uniform LDS.128 ----
#pragma unroll 8
        for (int k = 0; k < 64; k++) {
            const ulonglong2 w =
                *reinterpret_cast<const ulonglong2*>(&w2s[k * 128 + lane * 4]);
            const float* rowp = &my[k * EAT_STRIDE];
#pragma unroll
            for (int j = 0; j < T / 2; j++) {
                const ulonglong2 p =
                    *reinterpret_cast<const ulonglong2*>(&rowp[4 * j]);
                ffma2(acc0[2 * j],     w.x, p.x);
                ffma2(acc1[2 * j],     w.y, p.x);
                ffma2(acc0[2 * j + 1], w.x, p.y);
                ffma2(acc1[2 * j + 1], w.y, p.y);
            }
        }

        // ---- epilogue: gather A[src], bias, leaky_relu, scatter-add ----
        for (int t = 0; t < cnt; t++) {
            const long long e = base + t;
            const int s = idx[is64 ? 2 * e : e];
            const int d = idx[is64 ? 2 * (e + E) : (e + E)];
            const float4 av = __ldg(reinterpret_cast<const float4*>(
                &g_A[(size_t)s * 128 + lane * 4]));
            float o0, o1, o2, o3;
            upk2(acc0[t], o0, o1);
            upk2(acc1[t], o2, o3);
            o0 += av.x + cv.x;
            o1 += av.y + cv.y;
            o2 += av.z + cv.z;
            o3 += av.w + cv.w;
            o0 = (o0 > 0.f) ? o0 : 0.01f * o0;
            o1 = (o1 > 0.f) ? o1 : 0.01f * o1;
            o2 = (o2 > 0.f) ? o2 : 0.01f * o2;
            o3 = (o3 > 0.f) ? o3 : 0.01f * o3;
            float* p = &g_agg[(size_t)d * 128 + lane * 4];
            asm volatile("red.global.add.v4.f32 [%0], {%1, %2, %3, %4};" ::
                             "l"(p), "f"(o0), "f"(o1), "f"(o2), "f"(o3)
                         : "memory");
        }
        __syncwarp();  // protect staged tile (WAR) before next iteration
    }
}

// ---------------- epilogue: out = sigmoid(agg) * relu(beta) ----------------
__global__ void final_kernel(float* __restrict__ out, const float* __restrict__ beta,
                             int n4) {
    float b = beta[0];
    b = (b > 0.f) ? b : 0.f;
    int i = blockIdx.x * blockDim.x + threadIdx.x;
    const int stride = gridDim.x * blockDim.x;
    for (; i < n4; i += stride) {
        float4 v = reinterpret_cast<const float4*>(g_agg)[i];
        v.x = b / (1.f + __expf(-v.x));
        v.y = b / (1.f + __expf(-v.y));
        v.z = b / (1.f + __expf(-v.z));
        v.w = b / (1.f + __expf(-v.w));
        reinterpret_cast<float4*>(out)[i] = v;
    }
}

// ---------------- launch ----------------
extern "C" void kernel_launch(void* const* d_in, const int* in_sizes, int n_in,
                              void* d_out, int out_size) {
    const float* x    = (const float*)d_in[0];
    const int*   idx  = (const int*)d_in[1];   // int32 or int64 raw words
    const float* ea   = (const float*)d_in[2];
    const float* Wx   = (const float*)d_in[3];
    const float* bx   = (const float*)d_in[4];
    const float* We   = (const float*)d_in[5];
    const float* be   = (const float*)d_in[6];
    const float* Wm   = (const float*)d_in[7];
    const float* bm   = (const float*)d_in[8];
    const float* beta = (const float*)d_in[9];

    const int N = in_sizes[0] / 128;
    const int E = in_sizes[2] / 64;

    detect_kernel<<<1, 32>>>(idx);
    prep_kernel<<<193, 128>>>(Wx, bx, We, be, Wm, bm);
    zero_kernel<<<512, 256>>>(N * OUT / 4);

    cudaFuncSetAttribute(node_kernel, cudaFuncAttributeMaxDynamicSharedMemorySize,
                         128 * 128 * (int)sizeof(float));
    node_kernel<<<148 * 3, 256, 128 * 128 * sizeof(float)>>>(x, N);

    const int edge_smem = (64 * 128 + 128 + 8 * 64 * EAT_STRIDE) * (int)sizeof(float);
    cudaFuncSetAttribute(edge_kernel, cudaFuncAttributeMaxDynamicSharedMemorySize,
                         edge_smem);
    edge_kernel<<<148 * 2, 256, edge_smem>>>(ea, idx, E);

    final_kernel<<<512, 256>>>((float*)d_out, beta, N * OUT / 4);
}

// round 4
// speedup vs baseline: 2.1322x; 2.1322x over previous
#include <cuda_runtime.h>
#include <cuda_bf16.h>
#include <cstdint>

#define N_MAX   50000
#define OUT     128
#define EDIM    64

// ---------------- device scratch ----------------
__device__ __align__(16) float g_W1[128 * 128];
__device__ __align__(16) float g_W2[64 * 128];    // [k][n] fp32
__device__ __align__(16) float g_c[128];
__device__ __align__(16) float g_A[(size_t)N_MAX * OUT];
__device__ __align__(16) float g_agg[(size_t)N_MAX * OUT];
__device__ int g_is64;

// ---------------- helpers ----------------
__device__ __forceinline__ uint32_t smem_u32(const void* p) {
    uint32_t a;
    asm("{ .reg .u64 t; cvta.to.shared.u64 t, %1; cvt.u32.u64 %0, t; }" : "=r"(a) : "l"(p));
    return a;
}
#define SW128(off) ((off) ^ (((off) >> 3) & 0x70))

__device__ __forceinline__ void ldsm4(uint32_t& r0, uint32_t& r1, uint32_t& r2,
                                      uint32_t& r3, uint32_t a) {
    asm volatile("ldmatrix.sync.aligned.m8n8.x4.shared.b16 {%0,%1,%2,%3}, [%4];"
                 : "=r"(r0), "=r"(r1), "=r"(r2), "=r"(r3) : "r"(a));
}
__device__ __forceinline__ void mma16816(float* c, const uint32_t* a, uint32_t b0,
                                         uint32_t b1) {
    asm volatile(
        "mma.sync.aligned.m16n8k16.row.col.f32.bf16.bf16.f32 "
        "{%0,%1,%2,%3}, {%4,%5,%6,%7}, {%8,%9}, {%0,%1,%2,%3};"
        : "+f"(c[0]), "+f"(c[1]), "+f"(c[2]), "+f"(c[3])
        : "r"(a[0]), "r"(a[1]), "r"(a[2]), "r"(a[3]), "r"(b0), "r"(b1));
}

// f32x2 helpers (node kernel)
__device__ __forceinline__ unsigned long long pk2(float x, float y) {
    unsigned long long r;
    asm("mov.b64 %0, {%1, %2};" : "=l"(r) : "f"(x), "f"(y));
    return r;
}
__device__ __forceinline__ void upk2(unsigned long long v, float& x, float& y) {
    asm("mov.b64 {%0, %1}, %2;" : "=f"(x), "=f"(y) : "l"(v));
}
__device__ __forceinline__ void ffma2(unsigned long long& acc, unsigned long long w,
                                      unsigned long long a) {
    asm("fma.rn.f32x2 %0, %1, %2, %0;" : "+l"(acc) : "l"(w), "l"(a));
}

// ---------------- detect int64 vs int32 edge_index ----------------
__global__ void detect_kernel(const int* __restrict__ idx) {
    if (blockIdx.x == 0 && threadIdx.x == 0) {
        int ok = 1;
        for (int i = 1; i < 64; i += 2)
            if (idx[i] != 0) ok = 0;
        g_is64 = ok;
    }
}

// ---------------- fold weights ----------------
__global__ void prep_kernel(const float* __restrict__ Wx, const float* __restrict__ bx,
                            const float* __restrict__ We, const float* __restrict__ be,
                            const float* __restrict__ Wm, const float* __restrict__ bm) {
    __shared__ float row[128];
    __shared__ float row2[128];
    const int b = blockIdx.x;
    const int j = threadIdx.x;
    if (b < 128) {
        row[j] = Wx[b * 128 + j];
        __syncthreads();
        float s = 0.f;
#pragma unroll 8
        for (int k = 0; k < 128; k++) s = fmaf(row[k], Wm[k * 128 + j], s);
        g_W1[b * 128 + j] = s;
    } else if (b < 192) {
        const int i = b - 128;
        row[j] = We[i * 128 + j];
        __syncthreads();
        float s = 0.f;
#pragma unroll 8
        for (int k = 0; k < 128; k++) s = fmaf(row[k], Wm[(128 + k) * 128 + j], s);
        g_W2[i * 128 + j] = s;
    } else {
        row[j] = bx[j];
        row2[j] = be[j];
        __syncthreads();
        float s = bm[j];
#pragma unroll 8
        for (int k = 0; k < 128; k++) {
            s = fmaf(row[k], Wm[k * 128 + j], s);
            s = fmaf(row2[k], Wm[(128 + k) * 128 + j], s);
        }
        g_c[j] = s;
    }
}

__global__ void zero_kernel(int n4) {
    int i = blockIdx.x * blockDim.x + threadIdx.x;
    const int stride = gridDim.x * blockDim.x;
    float4 z = make_float4(0.f, 0.f, 0.f, 0.f);
    for (; i < n4; i += stride) reinterpret_cast<float4*>(g_agg)[i] = z;
}

// ---------------- node GEMM: A = x @ W1 (f32x2, T=8) ----------------
__global__ void __launch_bounds__(256) node_kernel(const float* __restrict__ x, int N) {
    extern __shared__ float w1s[];
    const int tid = threadIdx.x;
    for (int i = tid; i < 128 * 128; i += blockDim.x) w1s[i] = g_W1[i];
    __syncthreads();

    const int lane = tid & 31;
    const int gw = (blockIdx.x * blockDim.x + tid) >> 5;
    const int nw = (gridDim.x * blockDim.x) >> 5;
    constexpr int T = 8;

    for (int base = gw * T; base < N; base += nw * T) {
        const int cnt = min(T, N - base);
        float a[T][4];
#pragma unroll
        for (int t = 0; t < T; t++) {
            const int r = base + (t < cnt ? t : 0);
#pragma unroll
            for (int q = 0; q < 4; q++) a[t][q] = x[(size_t)r * 128 + q * 32 + lane];
        }
        unsigned long long acc0[T], acc1[T];
#pragma unroll
        for (int t = 0; t < T; t++) { acc0[t] = 0ull; acc1[t] = 0ull; }
#pragma unroll
        for (int q = 0; q < 4; q++) {
#pragma unroll 8
            for (int kk = 0; kk < 32; kk++) {
                const int k = q * 32 + kk;
                const float4 w = *reinterpret_cast<const float4*>(&w1s[k * 128 + lane * 4]);
                const unsigned long long w01 = pk2(w.x, w.y);
                const unsigned long long w23 = pk2(w.z, w.w);
#pragma unroll
                for (int t = 0; t < T; t++) {
                    const float av = __shfl_sync(0xffffffffu, a[t][q], kk);
                    const unsigned long long aa = pk2(av, av);
                    ffma2(acc0[t], w01, aa);
                    ffma2(acc1[t], w23, aa);
                }
            }
        }
#pragma unroll
        for (int t = 0; t < T; t++) {
            if (t < cnt) {
                float o0, o1, o2, o3;
                upk2(acc0[t], o0, o1);
                upk2(acc1[t], o2, o3);
                *reinterpret_cast<float4*>(&g_A[(size_t)(base + t) * 128 + lane * 4]) =
                    make_float4(o0, o1, o2, o3);
            }
        }
    }
}

// ---------------- edge kernel: bf16 mma.sync (hi/lo split) + scatter ----------------
// SMEM layout (dynamic, 1024B-aligned tiles):
//   [0,512)        bias cs[128] fp32
//   [1024)         B_hi: [n=128][k=64] bf16, SW128 rows   (16 KB)
//   [17408)        B_lo: same                             (16 KB)
//   [33792)        8 warp regions, stride 9216:
//                    A_hi [16m x 64k bf16 SW128] (2 KB) | A_lo (2 KB)
//                    aliased after use by D [16 x 136 fp32] (8704 B)
#define B_HI_OFF    1024
#define B_LO_OFF    17408
#define WARP_BASE   33792
#define WARP_STRIDE 9216
#define DSTRIDE     136
#define EDGE_SMEM   (33792 + 8 * 9216)

__global__ void __launch_bounds__(256, 2) edge_mma_kernel(const float* __restrict__ ea,
                                                          const int* __restrict__ idx,
                                                          int E, int ntiles) {
    extern __shared__ char smem[];
    const uint32_t sb = smem_u32(smem);
    const int tid = threadIdx.x;
    const int wid = tid >> 5;
    const int lane = tid & 31;
    const int is64 = g_is64;

    // build B tiles (hi/lo split of W2^T) + bias
    for (int i = tid; i < 64 * 128; i += 256) {
        const int k = i >> 7, n = i & 127;
        const float v = g_W2[i];
        const __nv_bfloat16 h = __float2bfloat16(v);
        const __nv_bfloat16 l = __float2bfloat16(v - __bfloat162float(h));
        const uint32_t off = (uint32_t)n * 128 + (uint32_t)k * 2;
        const uint32_t sw = SW128(off);
        *reinterpret_cast<__nv_bfloat16*>(smem + B_HI_OFF + sw) = h;
        *reinterpret_cast<__nv_bfloat16*>(smem + B_LO_OFF + sw) = l;
    }
    if (tid < 128) reinterpret_cast<float*>(smem)[tid] = g_c[tid];
    __syncthreads();

    const float4 cv = reinterpret_cast<const float4*>(smem)[lane];
    char* wbuf = smem + WARP_BASE + wid * WARP_STRIDE;
    const uint32_t wb32 = sb + WARP_BASE + wid * WARP_STRIDE;
    const float4* ea4 = reinterpret_cast<const float4*>(ea);

    // per-lane ldmatrix address components
    const int a_m = lane & 15;
    const int a_kb = ((lane >> 4) & 1) * 16;                 // A: k-byte sub-offset
    const int b_row = ((lane >= 16) ? 8 : 0) + (lane & 7);   // B: row within 16-n pair
    const int b_kb = ((lane >> 3) & 1) * 16;                 // B: k-byte sub-offset

    for (int tp = blockIdx.x; tp < ntiles; tp += gridDim.x) {
        const long long base_e = (long long)tp * 128 + wid * 16;

        // ---- stage this warp's 16 edges: hi/lo bf16, SW128 ----
#pragma unroll
        for (int i = 0; i < 8; i++) {
            const int f = i * 32 + lane;
            const int el = f >> 4;
            const int q = f & 15;
            long long e = base_e + el;
            if (e >= E) e = E - 1;
            const float4 v = __ldg(&ea4[e * 16 + q]);
            uint32_t h01, h23, l01, l23;
            asm("cvt.rn.bf16x2.f32 %0, %1, %2;" : "=r"(h01) : "f"(v.y), "f"(v.x));
            asm("cvt.rn.bf16x2.f32 %0, %1, %2;" : "=r"(h23) : "f"(v.w), "f"(v.z));
            const float hx = __uint_as_float(h01 << 16);
            const float hy = __uint_as_float(h01 & 0xffff0000u);
            const float hz = __uint_as_float(h23 << 16);
            const float hw = __uint_as_float(h23 & 0xffff0000u);
            asm("cvt.rn.bf16x2.f32 %0, %1, %2;" : "=r"(l01) : "f"(v.y - hy), "f"(v.x - hx));
            asm("cvt.rn.bf16x2.f32 %0, %1, %2;" : "=r"(l23) : "f"(v.w - hw), "f"(v.z - hz));
            const uint32_t sw = SW128((uint32_t)(el * 128 + q * 8));
            *reinterpret_cast<uint2*>(wbuf + sw) = make_uint2(h01, h23);
            *reinterpret_cast<uint2*>(wbuf + 2048 + sw) = make_uint2(l01, l23);
        }

        // ---- prefetch edge indices (lanes 0..15 hold edge 'lane') ----
        int sidx = 0, didx = 0;
        {
            const long long e = base_e + lane;
            if (lane < 16 && e < E) {
                sidx = idx[is64 ? 2 * e : e];
                didx = idx[is64 ? 2 * (e + E) : (e + E)];
            }
        }
        __syncwarp();

        // ---- load A fragments (hi/lo, 4 k-steps) ----
        uint32_t ah[4][4], al[4][4];
#pragma unroll
        for (int ks = 0; ks < 4; ks++) {
            const uint32_t addr = wb32 + SW128((uint32_t)(a_m * 128 + ks * 32 + a_kb));
            ldsm4(ah[ks][0], ah[ks][1], ah[ks][2], ah[ks][3], addr);
            ldsm4(al[ks][0], al[ks][1], al[ks][2], al[ks][3], addr + 2048);
        }
        __syncwarp();  // A smem region now reusable as D

        // ---- compute: 8 n-pairs, 3-term hi/lo mma; bounce acc to smem ----
        float* dbuf = reinterpret_cast<float*>(wbuf);
#pragma unroll
        for (int j = 0; j < 8; j++) {
            float acc0[4] = {0.f, 0.f, 0.f, 0.f};
            float acc1[4] = {0.f, 0.f, 0.f, 0.f};
#pragma unroll
            for (int ks = 0; ks < 4; ks++) {
                const uint32_t boff =
                    (uint32_t)((16 * j + b_row) * 128 + ks * 32 + b_kb);
                const uint32_t sw = SW128(boff);
                uint32_t bh0, bh1, bh2, bh3, bl0, bl1, bl2, bl3;
                ldsm4(bh0, bh1, bh2, bh3, sb + B_HI_OFF + sw);
                ldsm4(bl0, bl1, bl2, bl3, sb + B_LO_OFF + sw);
                mma16816(acc0, ah[ks], bh0, bh1);
                mma16816(acc0, ah[ks], bl0, bl1);
                mma16816(acc0, al[ks], bh0, bh1);
                mma16816(acc1, ah[ks], bh2, bh3);
                mma16816(acc1, ah[ks], bl2, bl3);
                mma16816(acc1, al[ks], bh2, bh3);
            }
            const int r0 = lane >> 2;
            const int c0 = j * 16 + 2 * (lane & 3);
            *reinterpret_cast<float2*>(dbuf + r0 * DSTRIDE + c0) =
                make_float2(acc0[0], acc0[1]);
            *reinterpret_cast<float2*>(dbuf + (r0 + 8) * DSTRIDE + c0) =
                make_float2(acc0[2], acc0[3]);
            *reinterpret_cast<float2*>(dbuf + r0 * DSTRIDE + c0 + 8) =
                make_float2(acc1[0], acc1[1]);
            *reinterpret_cast<float2*>(dbuf + (r0 + 8) * DSTRIDE + c0 + 8) =
                make_float2(acc1[2], acc1[3]);
        }
        __syncwarp();

        // ---- epilogue: gather A[src] + bias + leaky_relu + v4 scatter-add ----
#pragma unroll 4
        for (int t = 0; t < 16; t++) {
            if (base_e + t >= E) break;
            const int s = __shfl_sync(0xffffffffu, sidx, t);
            const int d = __shfl_sync(0xffffffffu, didx, t);
            const float4 dv =
                *reinterpret_cast<const float4*>(dbuf + t * DSTRIDE + lane * 4);
            const float4 av = __ldg(reinterpret_cast<const float4*>(
                &g_A[(size_t)s * 128 + lane * 4]));
            float o0 = dv.x + av.x + cv.x;
            float o1 = dv.y + av.y + cv.y;
            float o2 = dv.z + av.z + cv.z;
            float o3 = dv.w + av.w + cv.w;
            o0 = (o0 > 0.f) ? o0 : 0.01f * o0;
            o1 = (o1 > 0.f) ? o1 : 0.01f * o1;
            o2 = (o2 > 0.f) ? o2 : 0.01f * o2;
            o3 = (o3 > 0.f) ? o3 : 0.01f * o3;
            asm volatile("red.global.add.v4.f32 [%0], {%1, %2, %3, %4};" ::
                             "l"(&g_agg[(size_t)d * 128 + lane * 4]),
                             "f"(o0), "f"(o1), "f"(o2), "f"(o3)
                         : "memory");
        }
        __syncwarp();  // D/A region reused next iteration
    }
}

// ---------------- epilogue: out = sigmoid(agg) * relu(beta) ----------------
__global__ void final_kernel(float* __restrict__ out, const float* __restrict__ beta,
                             int n4) {
    float b = beta[0];
    b = (b > 0.f) ? b : 0.f;
    int i = blockIdx.x * blockDim.x + threadIdx.x;
    const int stride = gridDim.x * blockDim.x;
    for (; i < n4; i += stride) {
        float4 v = reinterpret_cast<const float4*>(g_agg)[i];
        v.x = b / (1.f + __expf(-v.x));
        v.y = b / (1.f + __expf(-v.y));
        v.z = b / (1.f + __expf(-v.z));
        v.w = b / (1.f + __expf(-v.w));
        reinterpret_cast<float4*>(out)[i] = v;
    }
}

// ---------------- launch ----------------
extern "C" void kernel_launch(void* const* d_in, const int* in_sizes, int n_in,
                              void* d_out, int out_size) {
    const float* x    = (const float*)d_in[0];
    const int*   idx  = (const int*)d_in[1];
    const float* ea   = (const float*)d_in[2];
    const float* Wx   = (const float*)d_in[3];
    const float* bx   = (const float*)d_in[4];
    const float* We   = (const float*)d_in[5];
    const float* be   = (const float*)d_in[6];
    const float* Wm   = (const float*)d_in[7];
    const float* bm   = (const float*)d_in[8];
    const float* beta = (const float*)d_in[9];

    const int N = in_sizes[0] / 128;
    const int E = in_sizes[2] / 64;
    const int ntiles = (E + 127) / 128;

    detect_kernel<<<1, 32>>>(idx);
    prep_kernel<<<193, 128>>>(Wx, bx, We, be, Wm, bm);
    zero_kernel<<<512, 256>>>(N * OUT / 4);

    cudaFuncSetAttribute(node_kernel, cudaFuncAttributeMaxDynamicSharedMemorySize,
                         128 * 128 * (int)sizeof(float));
    node_kernel<<<148 * 3, 256, 128 * 128 * sizeof(float)>>>(x, N);

    cudaFuncSetAttribute(edge_mma_kernel, cudaFuncAttributeMaxDynamicSharedMemorySize,
                         EDGE_SMEM);
    edge_mma_kernel<<<148 * 2, 256, EDGE_SMEM>>>(ea, idx, E, ntiles);

    final_kernel<<<512, 256>>>((float*)d_out, beta, N * OUT / 4);
}

// round 5
// speedup vs baseline: 2.3537x; 1.1039x over previous
#include <cuda_runtime.h>
#include <cuda_bf16.h>
#include <cstdint>

#define N_MAX   50000
#define OUT     128
#define EDIM    64

// ---------------- device scratch ----------------
__device__ __align__(16) float g_W1[128 * 128];
__device__ __align__(16) float g_W2[64 * 128];    // [k][n] fp32
__device__ __align__(16) float g_c[128];
__device__ __align__(16) float g_A[(size_t)N_MAX * OUT];
__device__ __align__(16) float g_agg[(size_t)N_MAX * OUT];
__device__ int g_is64;

// ---------------- helpers ----------------
__device__ __forceinline__ uint32_t smem_u32(const void* p) {
    uint32_t a;
    asm("{ .reg .u64 t; cvta.to.shared.u64 t, %1; cvt.u32.u64 %0, t; }" : "=r"(a) : "l"(p));
    return a;
}
#define SW128(off) ((off) ^ (((off) >> 3) & 0x70))

__device__ __forceinline__ void ldsm4(uint32_t& r0, uint32_t& r1, uint32_t& r2,
                                      uint32_t& r3, uint32_t a) {
    asm volatile("ldmatrix.sync.aligned.m8n8.x4.shared.b16 {%0,%1,%2,%3}, [%4];"
                 : "=r"(r0), "=r"(r1), "=r"(r2), "=r"(r3) : "r"(a));
}
__device__ __forceinline__ void mma16816(float* c, const uint32_t* a, uint32_t b0,
                                         uint32_t b1) {
    asm volatile(
        "mma.sync.aligned.m16n8k16.row.col.f32.bf16.bf16.f32 "
        "{%0,%1,%2,%3}, {%4,%5,%6,%7}, {%8,%9}, {%0,%1,%2,%3};"
        : "+f"(c[0]), "+f"(c[1]), "+f"(c[2]), "+f"(c[3])
        : "r"(a[0]), "r"(a[1]), "r"(a[2]), "r"(a[3]), "r"(b0), "r"(b1));
}
// split fp32x4 into hi/lo bf16x2 pairs
__device__ __forceinline__ void split4(const float4& v, uint32_t& h01, uint32_t& h23,
                                       uint32_t& l01, uint32_t& l23) {
    asm("cvt.rn.bf16x2.f32 %0, %1, %2;" : "=r"(h01) : "f"(v.y), "f"(v.x));
    asm("cvt.rn.bf16x2.f32 %0, %1, %2;" : "=r"(h23) : "f"(v.w), "f"(v.z));
    const float hx = __uint_as_float(h01 << 16);
    const float hy = __uint_as_float(h01 & 0xffff0000u);
    const float hz = __uint_as_float(h23 << 16);
    const float hw = __uint_as_float(h23 & 0xffff0000u);
    asm("cvt.rn.bf16x2.f32 %0, %1, %2;" : "=r"(l01) : "f"(v.y - hy), "f"(v.x - hx));
    asm("cvt.rn.bf16x2.f32 %0, %1, %2;" : "=r"(l23) : "f"(v.w - hw), "f"(v.z - hz));
}

// ---------------- detect int64 vs int32 edge_index ----------------
__global__ void detect_kernel(const int* __restrict__ idx) {
    if (blockIdx.x == 0 && threadIdx.x == 0) {
        int ok = 1;
        for (int i = 1; i < 64; i += 2)
            if (idx[i] != 0) ok = 0;
        g_is64 = ok;
    }
}

// ---------------- fold weights ----------------
__global__ void prep_kernel(const float* __restrict__ Wx, const float* __restrict__ bx,
                            const float* __restrict__ We, const float* __restrict__ be,
                            const float* __restrict__ Wm, const float* __restrict__ bm) {
    __shared__ float row[128];
    __shared__ float row2[128];
    const int b = blockIdx.x;
    const int j = threadIdx.x;
    if (b < 128) {
        row[j] = Wx[b * 128 + j];
        __syncthreads();
        float s = 0.f;
#pragma unroll 8
        for (int k = 0; k < 128; k++) s = fmaf(row[k], Wm[k * 128 + j], s);
        g_W1[b * 128 + j] = s;
    } else if (b < 192) {
        const int i = b - 128;
        row[j] = We[i * 128 + j];
        __syncthreads();
        float s = 0.f;
#pragma unroll 8
        for (int k = 0; k < 128; k++) s = fmaf(row[k], Wm[(128 + k) * 128 + j], s);
        g_W2[i * 128 + j] = s;
    } else {
        row[j] = bx[j];
        row2[j] = be[j];
        __syncthreads();
        float s = bm[j];
#pragma unroll 8
        for (int k = 0; k < 128; k++) {
            s = fmaf(row[k], Wm[k * 128 + j], s);
            s = fmaf(row2[k], Wm[(128 + k) * 128 + j], s);
        }
        g_c[j] = s;
    }
}

// ---------------- node GEMM via bf16 mma (hi/lo x3) + fused agg zeroing ----------------
// SMEM: B_hi [n=128][2x128B lines] 32KB | B_lo 32KB | 8 warp A regions (hi 4KB + lo 4KB)
#define NB_HI     0
#define NB_LO     32768
#define NW_BASE   65536
#define NW_STRIDE 8192
#define NODE_SMEM (65536 + 8 * 8192)

__global__ void __launch_bounds__(256) node_mma_kernel(const float* __restrict__ x,
                                                       int N, int ntiles, int n4) {
    extern __shared__ char smem[];
    const uint32_t sb = smem_u32(smem);
    const int tid = threadIdx.x;
    const int wid = tid >> 5;
    const int lane = tid & 31;

    // fused: zero the aggregation buffer (independent of GEMM)
    {
        const float4 z = make_float4(0.f, 0.f, 0.f, 0.f);
        const int stride = gridDim.x * blockDim.x;
        for (int i = blockIdx.x * blockDim.x + tid; i < n4; i += stride)
            reinterpret_cast<float4*>(g_agg)[i] = z;
    }

    // build B tiles: B[n][k] = W1[k][n], hi/lo bf16, rows split into 2x128B lines
    for (int i = tid; i < 128 * 128; i += 256) {
        const int k = i >> 7, n = i & 127;
        const float v = g_W1[i];
        const __nv_bfloat16 h = __float2bfloat16(v);
        const __nv_bfloat16 l = __float2bfloat16(v - __bfloat162float(h));
        const uint32_t off = (uint32_t)(n * 2 + (k >> 6)) * 128 + (uint32_t)(k & 63) * 2;
        const uint32_t sw = SW128(off);
        *reinterpret_cast<__nv_bfloat16*>(smem + NB_HI + sw) = h;
        *reinterpret_cast<__nv_bfloat16*>(smem + NB_LO + sw) = l;
    }
    __syncthreads();

    char* wbuf = smem + NW_BASE + wid * NW_STRIDE;
    const uint32_t wb32 = sb + NW_BASE + wid * NW_STRIDE;
    const float4* x4 = reinterpret_cast<const float4*>(x);

    const int a_m = lane & 15;
    const int a_kb = ((lane >> 4) & 1) * 16;
    const int b_row = ((lane >= 16) ? 8 : 0) + (lane & 7);
    const int b_kb = ((lane >> 3) & 1) * 16;

    for (int tp = blockIdx.x; tp < ntiles; tp += gridDim.x) {
        const int base_r = tp * 128 + wid * 16;

        // ---- stage 16 rows of x: hi/lo bf16, 2x128B lines per row ----
#pragma unroll
        for (int i = 0; i < 16; i++) {
            const int f = i * 32 + lane;
            const int el = f >> 5;   // row 0..15
            const int q = f & 31;    // float4 col 0..31
            int r = base_r + el;
            if (r >= N) r = N - 1;
            const float4 v = __ldg(&x4[(size_t)r * 32 + q]);
            uint32_t h01, h23, l01, l23;
            split4(v, h01, h23, l01, l23);
            const uint32_t off =
                (uint32_t)(el * 2 + (q >> 4)) * 128 + (uint32_t)(q & 15) * 8;
            const uint32_t sw = SW128(off);
            *reinterpret_cast<uint2*>(wbuf + sw) = make_uint2(h01, h23);
            *reinterpret_cast<uint2*>(wbuf + 4096 + sw) = make_uint2(l01, l23);
        }
        __syncwarp();

        // ---- load A fragments: 8 k-steps, hi/lo ----
        uint32_t ah[8][4], al[8][4];
#pragma unroll
        for (int ks = 0; ks < 8; ks++) {
            const uint32_t addr = wb32 + SW128((uint32_t)(
                (a_m * 2 + (ks >> 2)) * 128 + (ks & 3) * 32 + a_kb));
            ldsm4(ah[ks][0], ah[ks][1], ah[ks][2], ah[ks][3], addr);
            ldsm4(al[ks][0], al[ks][1], al[ks][2], al[ks][3], addr + 4096);
        }
        __syncwarp();

        // ---- compute in j-pairs (4 accumulator chains) and store direct ----
#pragma unroll
        for (int jp = 0; jp < 4; jp++) {
            const int j0 = jp * 2, j1 = jp * 2 + 1;
            float p0[4] = {0.f, 0.f, 0.f, 0.f}, p1[4] = {0.f, 0.f, 0.f, 0.f};
            float q0[4] = {0.f, 0.f, 0.f, 0.f}, q1[4] = {0.f, 0.f, 0.f, 0.f};
#pragma unroll
            for (int ks = 0; ks < 8; ks++) {
                const uint32_t base_off = (uint32_t)((ks >> 2) * 128 +
                                                     (ks & 3) * 32 + b_kb);
                const uint32_t sw0 = SW128((uint32_t)((16 * j0 + b_row) * 256) + base_off);
                const uint32_t sw1 = SW128((uint32_t)((16 * j1 + b_row) * 256) + base_off);
                uint32_t bh0, bh1, bh2, bh3, bl0, bl1, bl2, bl3;
                uint32_t ch0, ch1, ch2, ch3, cl0, cl1, cl2, cl3;
                ldsm4(bh0, bh1, bh2, bh3, sb + NB_HI + sw0);
                ldsm4(bl0, bl1, bl2, bl3, sb + NB_LO + sw0);
                ldsm4(ch0, ch1, ch2, ch3, sb + NB_HI + sw1);
                ldsm4(cl0, cl1, cl2, cl3, sb + NB_LO + sw1);
                mma16816(p0, ah[ks], bh0, bh1);
                mma16816(p1, ah[ks], bh2, bh3);
                mma16816(q0, ah[ks], ch0, ch1);
                mma16816(q1, ah[ks], ch2, ch3);
                mma16816(p0, ah[ks], bl0, bl1);
                mma16816(p1, ah[ks], bl2, bl3);
                mma16816(q0, ah[ks], cl0, cl1);
                mma16816(q1, ah[ks], cl2, cl3);
                mma16816(p0, al[ks], bh0, bh1);
                mma16816(p1, al[ks], bh2, bh3);
                mma16816(q0, al[ks], ch0, ch1);
                mma16816(q1, al[ks], ch2, ch3);
            }
            const int r0 = base_r + (lane >> 2);
            const int c0 = 2 * (lane & 3);
            if (r0 < N) {
                float* p = &g_A[(size_t)r0 * 128];
                *reinterpret_cast<float2*>(p + j0 * 16 + c0) = make_float2(p0[0], p0[1]);
                *reinterpret_cast<float2*>(p + j0 * 16 + c0 + 8) = make_float2(p1[0], p1[1]);
                *reinterpret_cast<float2*>(p + j1 * 16 + c0) = make_float2(q0[0], q0[1]);
                *reinterpret_cast<float2*>(p + j1 * 16 + c0 + 8) = make_float2(q1[0], q1[1]);
            }
            if (r0 + 8 < N) {
                float* p = &g_A[(size_t)(r0 + 8) * 128];
                *reinterpret_cast<float2*>(p + j0 * 16 + c0) = make_float2(p0[2], p0[3]);
                *reinterpret_cast<float2*>(p + j0 * 16 + c0 + 8) = make_float2(p1[2], p1[3]);
                *reinterpret_cast<float2*>(p + j1 * 16 + c0) = make_float2(q0[2], q0[3]);
                *reinterpret_cast<float2*>(p + j1 * 16 + c0 + 8) = make_float2(q1[2], q1[3]);
            }
        }
        __syncwarp();  // A staging reused next iteration
    }
}

// ---------------- edge kernel: bf16 mma.sync (hi/lo split) + scatter ----------------
#define B_HI_OFF    1024
#define B_LO_OFF    17408
#define WARP_BASE   33792
#define WARP_STRIDE 9216
#define DSTRIDE     136
#define EDGE_SMEM   (33792 + 8 * 9216)

__global__ void __launch_bounds__(256, 2) edge_mma_kernel(const float* __restrict__ ea,
                                                          const int* __restrict__ idx,
                                                          int E, int ntiles) {
    extern __shared__ char smem[];
    const uint32_t sb = smem_u32(smem);
    const int tid = threadIdx.x;
    const int wid = tid >> 5;
    const int lane = tid & 31;
    const int is64 = g_is64;

    // build B tiles (hi/lo split of W2^T) + bias
    for (int i = tid; i < 64 * 128; i += 256) {
        const int k = i >> 7, n = i & 127;
        const float v = g_W2[i];
        const __nv_bfloat16 h = __float2bfloat16(v);
        const __nv_bfloat16 l = __float2bfloat16(v - __bfloat162float(h));
        const uint32_t off = (uint32_t)n * 128 + (uint32_t)k * 2;
        const uint32_t sw = SW128(off);
        *reinterpret_cast<__nv_bfloat16*>(smem + B_HI_OFF + sw) = h;
        *reinterpret_cast<__nv_bfloat16*>(smem + B_LO_OFF + sw) = l;
    }
    if (tid < 128) reinterpret_cast<float*>(smem)[tid] = g_c[tid];
    __syncthreads();

    const float4 cv = reinterpret_cast<const float4*>(smem)[lane];
    char* wbuf = smem + WARP_BASE + wid * WARP_STRIDE;
    const uint32_t wb32 = sb + WARP_BASE + wid * WARP_STRIDE;
    const float4* ea4 = reinterpret_cast<const float4*>(ea);

    const int a_m = lane & 15;
    const int a_kb = ((lane >> 4) & 1) * 16;
    const int b_row = ((lane >= 16) ? 8 : 0) + (lane & 7);
    const int b_kb = ((lane >> 3) & 1) * 16;

    for (int tp = blockIdx.x; tp < ntiles; tp += gridDim.x) {
        const long long base_e = (long long)tp * 128 + wid * 16;

        // ---- stage this warp's 16 edges: hi/lo bf16, SW128 ----
#pragma unroll
        for (int i = 0; i < 8; i++) {
            const int f = i * 32 + lane;
            const int el = f >> 4;
            const int q = f & 15;
            long long e = base_e + el;
            if (e >= E) e = E - 1;
            const float4 v = __ldg(&ea4[e * 16 + q]);
            uint32_t h01, h23, l01, l23;
            split4(v, h01, h23, l01, l23);
            const uint32_t sw = SW128((uint32_t)(el * 128 + q * 8));
            *reinterpret_cast<uint2*>(wbuf + sw) = make_uint2(h01, h23);
            *reinterpret_cast<uint2*>(wbuf + 2048 + sw) = make_uint2(l01, l23);
        }

        // ---- prefetch edge indices (lanes 0..15 hold edge 'lane') ----
        int sidx = 0, didx = 0;
        {
            const long long e = base_e + lane;
            if (lane < 16 && e < E) {
                sidx = idx[is64 ? 2 * e : e];
                didx = idx[is64 ? 2 * (e + E) : (e + E)];
            }
        }
        __syncwarp();

        // ---- load A fragments (hi/lo, 4 k-steps) ----
        uint32_t ah[4][4], al[4][4];
#pragma unroll
        for (int ks = 0; ks < 4; ks++) {
            const uint32_t addr = wb32 + SW128((uint32_t)(a_m * 128 + ks * 32 + a_kb));
            ldsm4(ah[ks][0], ah[ks][1], ah[ks][2], ah[ks][3], addr);
            ldsm4(al[ks][0], al[ks][1], al[ks][2], al[ks][3], addr + 2048);
        }
        __syncwarp();  // A smem region now reusable as D

        // ---- compute: 8 n-pairs, 3-term hi/lo mma; bounce acc to smem ----
        float* dbuf = reinterpret_cast<float*>(wbuf);
#pragma unroll
        for (int j = 0; j < 8; j++) {
            float acc0[4] = {0.f, 0.f, 0.f, 0.f};
            float acc1[4] = {0.f, 0.f, 0.f, 0.f};
#pragma unroll
            for (int ks = 0; ks < 4; ks++) {
                const uint32_t boff =
                    (uint32_t)((16 * j + b_row) * 128 + ks * 32 + b_kb);
                const uint32_t sw = SW128(boff);
                uint32_t bh0, bh1, bh2, bh3, bl0, bl1, bl2, bl3;
                ldsm4(bh0, bh1, bh2, bh3, sb + B_HI_OFF + sw);
                ldsm4(bl0, bl1, bl2, bl3, sb + B_LO_OFF + sw);
                mma16816(acc0, ah[ks], bh0, bh1);
                mma16816(acc0, ah[ks], bl0, bl1);
                mma16816(acc0, al[ks], bh0, bh1);
                mma16816(acc1, ah[ks], bh2, bh3);
                mma16816(acc1, ah[ks], bl2, bl3);
                mma16816(acc1, al[ks], bh2, bh3);
            }
            const int r0 = lane >> 2;
            const int c0 = j * 16 + 2 * (lane & 3);
            *reinterpret_cast<float2*>(dbuf + r0 * DSTRIDE + c0) =
                make_float2(acc0[0], acc0[1]);
            *reinterpret_cast<float2*>(dbuf + (r0 + 8) * DSTRIDE + c0) =
                make_float2(acc0[2], acc0[3]);
            *reinterpret_cast<float2*>(dbuf + r0 * DSTRIDE + c0 + 8) =
                make_float2(acc1[0], acc1[1]);
            *reinterpret_cast<float2*>(dbuf + (r0 + 8) * DSTRIDE + c0 + 8) =
                make_float2(acc1[2], acc1[3]);
        }
        __syncwarp();

        // ---- epilogue: gather A[src] + bias + leaky_relu + v4 scatter-add ----
#pragma unroll 4
        for (int t = 0; t < 16; t++) {
            if (base_e + t >= E) break;
            const int s = __shfl_sync(0xffffffffu, sidx, t);
            const int d = __shfl_sync(0xffffffffu, didx, t);
            const float4 dv =
                *reinterpret_cast<const float4*>(dbuf + t * DSTRIDE + lane * 4);
            const float4 av = __ldg(reinterpret_cast<const float4*>(
                &g_A[(size_t)s * 128 + lane * 4]));
            float o0 = dv.x + av.x + cv.x;
            float o1 = dv.y + av.y + cv.y;
            float o2 = dv.z + av.z + cv.z;
            float o3 = dv.w + av.w + cv.w;
            o0 = (o0 > 0.f) ? o0 : 0.01f * o0;
            o1 = (o1 > 0.f) ? o1 : 0.01f * o1;
            o2 = (o2 > 0.f) ? o2 : 0.01f * o2;
            o3 = (o3 > 0.f) ? o3 : 0.01f * o3;
            asm volatile("red.global.add.v4.f32 [%0], {%1, %2, %3, %4};" ::
                             "l"(&g_agg[(size_t)d * 128 + lane * 4]),
                             "f"(o0), "f"(o1), "f"(o2), "f"(o3)
                         : "memory");
        }
        __syncwarp();  // D/A region reused next iteration
    }
}

// ---------------- epilogue: out = sigmoid(agg) * relu(beta) ----------------
__global__ void final_kernel(float* __restrict__ out, const float* __restrict__ beta,
                             int n4) {
    float b = beta[0];
    b = (b > 0.f) ? b : 0.f;
    int i = blockIdx.x * blockDim.x + threadIdx.x;
    const int stride = gridDim.x * blockDim.x;
    for (; i < n4; i += stride) {
        float4 v = reinterpret_cast<const float4*>(g_agg)[i];
        v.x = b / (1.f + __expf(-v.x));
        v.y = b / (1.f + __expf(-v.y));
        v.z = b / (1.f + __expf(-v.z));
        v.w = b / (1.f + __expf(-v.w));
        reinterpret_cast<float4*>(out)[i] = v;
    }
}

// ---------------- launch ----------------
extern "C" void kernel_launch(void* const* d_in, const int* in_sizes, int n_in,
                              void* d_out, int out_size) {
    const float* x    = (const float*)d_in[0];
    const int*   idx  = (const int*)d_in[1];
    const float* ea   = (const float*)d_in[2];
    const float* Wx   = (const float*)d_in[3];
    const float* bx   = (const float*)d_in[4];
    const float* We   = (const float*)d_in[5];
    const float* be   = (const float*)d_in[6];
    const float* Wm   = (const float*)d_in[7];
    const float* bm   = (const float*)d_in[8];
    const float* beta = (const float*)d_in[9];

    const int N = in_sizes[0] / 128;
    const int E = in_sizes[2] / 64;
    const int n_tiles_node = (N + 127) / 128;
    const int n_tiles_edge = (E + 127) / 128;
    const int n4 = N * OUT / 4;

    detect_kernel<<<1, 32>>>(idx);
    prep_kernel<<<193, 128>>>(Wx, bx, We, be, Wm, bm);

    cudaFuncSetAttribute(node_mma_kernel, cudaFuncAttributeMaxDynamicSharedMemorySize,
                         NODE_SMEM);
    node_mma_kernel<<<n_tiles_node, 256, NODE_SMEM>>>(x, N, n_tiles_node, n4);

    cudaFuncSetAttribute(edge_mma_kernel, cudaFuncAttributeMaxDynamicSharedMemorySize,
                         EDGE_SMEM);
    edge_mma_kernel<<<148 * 2, 256, EDGE_SMEM>>>(ea, idx, E, n_tiles_edge);

    final_kernel<<<512, 256>>>((float*)d_out, beta, n4);
}